// round 3
// baseline (speedup 1.0000x reference)
#include <cuda_runtime.h>
#include <cuda_bf16.h>
#include <cstdint>

using bf16 = __nv_bfloat16;

#define DEVI __device__ __forceinline__

constexpr int Bc = 4;      // batch
constexpr int Nt = 2048;   // tokens
constexpr int Dc = 1024;   // model dim
constexpr int Fc = 4096;   // ffn dim
constexpr int Mrows = Bc * Nt;   // 8192

// ---- conv GEMM config (proven R1 layout) ----
constexpr int BM = 128, BN = 128, BK = 32;
constexpr int SA_ST   = BK + 8;    // 40
constexpr int SBKN_ST = BN + 8;    // 136
constexpr int NTHREADS = 256;

// ---- MLP GEMM config: 128x256 CTA tile, 8 warps @ 64x64, 3-stage ----
constexpr int GBM = 128, GBN = 256, GBK = 32;
constexpr int STAGES = 3;
constexpr int SA_BYTES = GBM * SA_ST * 2;   // 10240
constexpr int SB_BYTES = GBN * SA_ST * 2;   // 20480
constexpr int SMEM_MLP = STAGES * (SA_BYTES + SB_BYTES);  // 92160

// ---------------- scratch ----------------------------------------------------
__device__ __align__(16) bf16  g_T[(size_t)Nt * Nt];
__device__ __align__(16) bf16  g_xb[(size_t)Bc * Nt * Dc];
__device__ __align__(16) float g_y1[(size_t)Bc * Nt * Dc];
__device__ __align__(16) float g_x1[(size_t)Bc * Nt * Dc];
__device__ __align__(16) bf16  g_x1b[(size_t)Bc * Nt * Dc];
__device__ __align__(16) bf16  g_W1b[(size_t)Fc * Dc];
__device__ __align__(16) bf16  g_W2b[(size_t)Dc * Fc];
__device__ __align__(16) bf16  g_H[(size_t)Bc * Nt * Fc];
__device__ __align__(16) float g_y2[(size_t)Bc * Nt * Dc];

// ---------------- PTX helpers -------------------------------------------------
DEVI uint32_t smem_u32(const void* p) {
    return static_cast<uint32_t>(__cvta_generic_to_shared(p));
}
DEVI void cp_async16(uint32_t sdst, const void* gsrc) {
    asm volatile("cp.async.cg.shared.global [%0], [%1], 16;\n" :: "r"(sdst), "l"(gsrc));
}
DEVI void cp_commit() { asm volatile("cp.async.commit_group;\n"); }
template <int N> DEVI void cp_wait() {
    asm volatile("cp.async.wait_group %0;\n" :: "n"(N));
}
DEVI void ldmx4(uint32_t& r0, uint32_t& r1, uint32_t& r2, uint32_t& r3, uint32_t a) {
    asm volatile("ldmatrix.sync.aligned.m8n8.x4.shared.b16 {%0,%1,%2,%3}, [%4];\n"
                 : "=r"(r0), "=r"(r1), "=r"(r2), "=r"(r3) : "r"(a));
}
DEVI void ldmx4t(uint32_t& r0, uint32_t& r1, uint32_t& r2, uint32_t& r3, uint32_t a) {
    asm volatile("ldmatrix.sync.aligned.m8n8.x4.trans.shared.b16 {%0,%1,%2,%3}, [%4];\n"
                 : "=r"(r0), "=r"(r1), "=r"(r2), "=r"(r3) : "r"(a));
}
DEVI void mma16816(float c[4], const uint32_t a[4], const uint32_t b[2]) {
    asm volatile(
        "mma.sync.aligned.m16n8k16.row.col.f32.bf16.bf16.f32 "
        "{%0,%1,%2,%3}, {%4,%5,%6,%7}, {%8,%9}, {%0,%1,%2,%3};\n"
        : "+f"(c[0]), "+f"(c[1]), "+f"(c[2]), "+f"(c[3])
        : "r"(a[0]), "r"(a[1]), "r"(a[2]), "r"(a[3]), "r"(b[0]), "r"(b[1]));
}
DEVI float gelu_exact(float v) {
    return 0.5f * v * (1.0f + erff(v * 0.70710678118654752f));
}

// ---------------- prep kernels ----------------------------------------------
template <int W>
__global__ void cvt_kernel(const float* __restrict__ src, int n4)
{
    bf16* dst = (W == 0) ? g_xb : (W == 1 ? g_W1b : g_W2b);
    int i = blockIdx.x * blockDim.x + threadIdx.x;
    if (i < n4) {
        float4 v = reinterpret_cast<const float4*>(src)[i];
        __nv_bfloat162* d2 = reinterpret_cast<__nv_bfloat162*>(dst) + 2 * (size_t)i;
        d2[0] = __floats2bfloat162_rn(v.x, v.y);
        d2[1] = __floats2bfloat162_rn(v.z, v.w);
    }
}

__global__ void buildT_kernel(const float* __restrict__ w)
{
    int i = blockIdx.x * blockDim.x + threadIdx.x;
    int n = i >> 11;
    int m = i & (Nt - 1);
    float v = (m <= n) ? w[n - m] : 0.0f;
    g_T[i] = __float2bfloat16(v);
}

// ---------------- conv GEMM (mma.sync, triangular K skip) ---------------------
__global__ void __launch_bounds__(NTHREADS) conv_gemm_kernel(
    const float* __restrict__ x, const float* __restrict__ scale)
{
    constexpr int K = Nt;
    constexpr int Nc = Dc;

    const bf16* __restrict__ A  = g_T;
    const bf16* __restrict__ Bp = g_xb + (size_t)blockIdx.z * Nt * Dc;

    __shared__ __align__(16) bf16 sA[2][BM * SA_ST];
    __shared__ __align__(16) bf16 sB[2][BK * SBKN_ST];

    const int tid  = threadIdx.x;
    const int bm0  = blockIdx.y * BM;
    const int bn0  = blockIdx.x * BN;
    const int wid  = tid >> 5;
    const int lane = tid & 31;
    const int wm   = (wid & 3) * 32;
    const int wn   = (wid >> 2) * 64;
    const int kmax = (bm0 + BM) / BK;   // lower-triangular skip

    float acc[2][8][4];
#pragma unroll
    for (int i = 0; i < 2; i++)
#pragma unroll
        for (int j = 0; j < 8; j++)
#pragma unroll
            for (int q = 0; q < 4; q++) acc[i][j][q] = 0.0f;

    auto load_tiles = [&](int s, int kt) {
        const bf16* Ag = A + (size_t)bm0 * K + (size_t)kt * BK;
#pragma unroll
        for (int i = 0; i < 2; i++) {
            int ch  = tid + i * NTHREADS;
            int row = ch >> 2;
            int col = (ch & 3) * 8;
            cp_async16(smem_u32(&sA[s][row * SA_ST + col]), Ag + (size_t)row * K + col);
        }
        const bf16* Bg = Bp + (size_t)(kt * BK) * Nc + bn0;
#pragma unroll
        for (int i = 0; i < 2; i++) {
            int ch  = tid + i * NTHREADS;
            int row = ch >> 4;
            int col = (ch & 15) * 8;
            cp_async16(smem_u32(&sB[s][row * SBKN_ST + col]), Bg + (size_t)row * Nc + col);
        }
        cp_commit();
    };

    load_tiles(0, 0);

    for (int kt = 0; kt < kmax; kt++) {
        const int s = kt & 1;
        if (kt + 1 < kmax) { load_tiles(s ^ 1, kt + 1); cp_wait<1>(); }
        else               { cp_wait<0>(); }
        __syncthreads();

#pragma unroll
        for (int kk = 0; kk < BK; kk += 16) {
            uint32_t a[2][4];
#pragma unroll
            for (int i = 0; i < 2; i++) {
                const bf16* p = &sA[s][(wm + i * 16 + (lane & 15)) * SA_ST
                                       + kk + (lane >> 4) * 8];
                ldmx4(a[i][0], a[i][1], a[i][2], a[i][3], smem_u32(p));
            }
            uint32_t b[8][2];
#pragma unroll
            for (int j = 0; j < 8; j += 2) {
                uint32_t r0, r1, r2, r3;
                const bf16* p = &sB[s][(kk + (lane & 15)) * SBKN_ST
                                       + wn + j * 8 + (lane >> 4) * 8];
                ldmx4t(r0, r1, r2, r3, smem_u32(p));
                b[j][0] = r0; b[j][1] = r1; b[j + 1][0] = r2; b[j + 1][1] = r3;
            }
#pragma unroll
            for (int i = 0; i < 2; i++)
#pragma unroll
                for (int j = 0; j < 8; j++)
                    mma16816(acc[i][j], a[i], b[j]);
        }
        __syncthreads();
    }

    const int rbase = bm0 + wm + (lane >> 2);
    const int cbase = bn0 + wn + (lane & 3) * 2;
#pragma unroll
    for (int i = 0; i < 2; i++)
#pragma unroll
        for (int j = 0; j < 8; j++)
#pragma unroll
            for (int h = 0; h < 2; h++) {
                const int r = rbase + i * 16 + h * 8;
                const int c = cbase + j * 8;
                const size_t o = (size_t)blockIdx.z * (Nt * Dc) + (size_t)r * Dc + c;
                const float sc = scale[r];
                float2 ov = make_float2(x[o] + acc[i][j][h * 2] * sc,
                                        x[o + 1] + acc[i][j][h * 2 + 1] * sc);
                *reinterpret_cast<float2*>(g_y1 + o) = ov;
            }
}

// ---------------- MLP GEMM (mma.sync, 128x256, 64x64 warps, 3-stage) ----------
// EPI 1: A=g_x1b [8192,1024], B=g_W1b [4096,1024] -> g_H = bf16(gelu(acc+b1))
// EPI 2: A=g_H   [8192,4096], B=g_W2b [1024,4096] -> g_y2 = g_x1 + s*(acc+b2)
template <int EPI>
__global__ void __launch_bounds__(NTHREADS, 1) mlp_gemm_kernel(
    const float* __restrict__ bias, const float* __restrict__ scl)
{
    constexpr int K  = (EPI == 1) ? Dc : Fc;
    constexpr int KT = K / GBK;

    extern __shared__ __align__(16) bf16 smem[];
    bf16* sA = smem;                               // [STAGES][GBM*SA_ST]
    bf16* sB = smem + STAGES * GBM * SA_ST;        // [STAGES][GBN*SA_ST]

    const bf16* __restrict__ A = (EPI == 1) ? g_x1b : g_H;
    const bf16* __restrict__ B = (EPI == 1) ? g_W1b : g_W2b;

    const int tid  = threadIdx.x;
    const int wid  = tid >> 5;
    const int lane = tid & 31;
    const int bm0  = blockIdx.y * GBM;
    const int bn0  = blockIdx.x * GBN;
    const int wm   = (wid & 1) * 64;    // 2 warps along M
    const int wn   = (wid >> 1) * 64;   // 4 warps along N

    float acc[4][8][4];
#pragma unroll
    for (int i = 0; i < 4; i++)
#pragma unroll
        for (int j = 0; j < 8; j++)
#pragma unroll
            for (int q = 0; q < 4; q++) acc[i][j][q] = 0.0f;

    auto load_tiles = [&](int s, int kt) {
        const bf16* Ag = A + (size_t)bm0 * K + (size_t)kt * GBK;
        bf16* sAs = sA + s * (GBM * SA_ST);
#pragma unroll
        for (int i = 0; i < 2; i++) {               // 512 chunks: 128 rows x 4
            int ch  = tid + i * NTHREADS;
            int row = ch >> 2;
            int col = (ch & 3) * 8;
            cp_async16(smem_u32(&sAs[row * SA_ST + col]), Ag + (size_t)row * K + col);
        }
        const bf16* Bg = B + (size_t)bn0 * K + (size_t)kt * GBK;
        bf16* sBs = sB + s * (GBN * SA_ST);
#pragma unroll
        for (int i = 0; i < 4; i++) {               // 1024 chunks: 256 rows x 4
            int ch  = tid + i * NTHREADS;
            int row = ch >> 2;
            int col = (ch & 3) * 8;
            cp_async16(smem_u32(&sBs[row * SA_ST + col]), Bg + (size_t)row * K + col);
        }
        cp_commit();
    };

    load_tiles(0, 0);
    load_tiles(1, 1);

    for (int kt = 0; kt < KT; kt++) {
        const int s = kt % STAGES;
        if (kt + 2 < KT) { load_tiles((kt + 2) % STAGES, kt + 2); cp_wait<2>(); }
        else if (kt + 1 < KT) { cp_wait<1>(); }
        else { cp_wait<0>(); }
        __syncthreads();

        const bf16* sAs = sA + s * (GBM * SA_ST);
        const bf16* sBs = sB + s * (GBN * SA_ST);

#pragma unroll
        for (int kk = 0; kk < GBK; kk += 16) {
            uint32_t a[4][4];
#pragma unroll
            for (int i = 0; i < 4; i++) {
                const bf16* p = &sAs[(wm + i * 16 + (lane & 15)) * SA_ST
                                     + kk + (lane >> 4) * 8];
                ldmx4(a[i][0], a[i][1], a[i][2], a[i][3], smem_u32(p));
            }
            uint32_t b[8][2];
#pragma unroll
            for (int j = 0; j < 8; j += 2) {
                uint32_t r0, r1, r2, r3;
                int rr = wn + j * 8 + ((lane >> 4) << 3) + (lane & 7);
                int cc = kk + ((lane >> 3) & 1) * 8;
                const bf16* p = &sBs[rr * SA_ST + cc];
                ldmx4(r0, r1, r2, r3, smem_u32(p));
                b[j][0] = r0; b[j][1] = r1; b[j + 1][0] = r2; b[j + 1][1] = r3;
            }
#pragma unroll
            for (int i = 0; i < 4; i++)
#pragma unroll
                for (int j = 0; j < 8; j++)
                    mma16816(acc[i][j], a[i], b[j]);
        }
        __syncthreads();
    }

    // ---------------- epilogue ----------------
    float sscal = 0.0f;
    if constexpr (EPI == 2) sscal = scl[0];
    const int rbase = bm0 + wm + (lane >> 2);
    const int cbase = bn0 + wn + (lane & 3) * 2;

#pragma unroll
    for (int i = 0; i < 4; i++) {
#pragma unroll
        for (int j = 0; j < 8; j++) {
#pragma unroll
            for (int h = 0; h < 2; h++) {
                const int r = rbase + i * 16 + h * 8;
                const int c = cbase + j * 8;
                const float v0 = acc[i][j][h * 2 + 0];
                const float v1 = acc[i][j][h * 2 + 1];
                if constexpr (EPI == 1) {
                    const size_t o = (size_t)r * Fc + c;
                    __nv_bfloat162 hv = __floats2bfloat162_rn(
                        gelu_exact(v0 + bias[c]), gelu_exact(v1 + bias[c + 1]));
                    *reinterpret_cast<__nv_bfloat162*>(g_H + o) = hv;
                } else {
                    const size_t o = (size_t)r * Dc + c;
                    float2 xv = *reinterpret_cast<const float2*>(g_x1 + o);
                    float2 ov = make_float2(xv.x + sscal * (v0 + bias[c]),
                                            xv.y + sscal * (v1 + bias[c + 1]));
                    *reinterpret_cast<float2*>(g_y2 + o) = ov;
                }
            }
        }
    }
}

// ---------------- LayerNorm ---------------------------------------------------
template <int WHICH>
__global__ void __launch_bounds__(256) ln_kernel(
    const float* __restrict__ lw, const float* __restrict__ lb,
    float* __restrict__ outp)
{
    const float* __restrict__ in = (WHICH == 1) ? g_y1 : g_y2;
    const size_t row = blockIdx.x;
    const int t = threadIdx.x;

    float4 v = reinterpret_cast<const float4*>(in + row * Dc)[t];
    float s = v.x + v.y + v.z + v.w;
    float q = v.x * v.x + v.y * v.y + v.z * v.z + v.w * v.w;
#pragma unroll
    for (int o = 16; o > 0; o >>= 1) {
        s += __shfl_xor_sync(0xffffffffu, s, o);
        q += __shfl_xor_sync(0xffffffffu, q, o);
    }
    __shared__ float red[16];
    if ((t & 31) == 0) { red[t >> 5] = s; red[8 + (t >> 5)] = q; }
    __syncthreads();
    s = 0.0f; q = 0.0f;
#pragma unroll
    for (int i = 0; i < 8; i++) { s += red[i]; q += red[8 + i]; }

    const float mu  = s * (1.0f / Dc);
    const float inv = rsqrtf(q * (1.0f / Dc) - mu * mu + 1e-5f);
    const int c = t * 4;
    const float o0 = (v.x - mu) * inv * lw[c + 0] + lb[c + 0];
    const float o1 = (v.y - mu) * inv * lw[c + 1] + lb[c + 1];
    const float o2 = (v.z - mu) * inv * lw[c + 2] + lb[c + 2];
    const float o3 = (v.w - mu) * inv * lw[c + 3] + lb[c + 3];

    if constexpr (WHICH == 1) {
        reinterpret_cast<float4*>(g_x1 + row * Dc)[t] = make_float4(o0, o1, o2, o3);
        __nv_bfloat162* pb = reinterpret_cast<__nv_bfloat162*>(g_x1b + row * Dc) + t * 2;
        pb[0] = __floats2bfloat162_rn(o0, o1);
        pb[1] = __floats2bfloat162_rn(o2, o3);
    } else {
        reinterpret_cast<float4*>(outp + row * Dc)[t] = make_float4(o0, o1, o2, o3);
    }
}

// ---------------- launch --------------------------------------------------------
extern "C" void kernel_launch(void* const* d_in, const int* in_sizes, int n_in,
                              void* d_out, int out_size)
{
    const float* x       = (const float*)d_in[0];
    const float* weights = (const float*)d_in[1];
    const float* scale   = (const float*)d_in[2];
    const float* ln1w    = (const float*)d_in[3];
    const float* ln1b    = (const float*)d_in[4];
    const float* W1      = (const float*)d_in[5];
    const float* b1      = (const float*)d_in[6];
    const float* W2      = (const float*)d_in[7];
    const float* b2      = (const float*)d_in[8];
    const float* scalar  = (const float*)d_in[9];
    const float* ln2w    = (const float*)d_in[10];
    const float* ln2b    = (const float*)d_in[11];
    float* out = (float*)d_out;

    cudaFuncSetAttribute(mlp_gemm_kernel<1>,
                         cudaFuncAttributeMaxDynamicSharedMemorySize, SMEM_MLP);
    cudaFuncSetAttribute(mlp_gemm_kernel<2>,
                         cudaFuncAttributeMaxDynamicSharedMemorySize, SMEM_MLP);

    // prep
    {
        int n4x = Bc * Nt * Dc / 4;
        cvt_kernel<0><<<(n4x + 255) / 256, 256>>>(x, n4x);
        int n4w = Fc * Dc / 4;
        cvt_kernel<1><<<(n4w + 255) / 256, 256>>>(W1, n4w);
        cvt_kernel<2><<<(n4w + 255) / 256, 256>>>(W2, n4w);
        buildT_kernel<<<(Nt * Nt) / 256, 256>>>(weights);
    }

    // conv (triangular Toeplitz GEMM) + residual scale-add
    conv_gemm_kernel<<<dim3(Dc / BN, Nt / BM, Bc), NTHREADS>>>(x, scale);
    // LN1
    ln_kernel<1><<<Bc * Nt, 256>>>(ln1w, ln1b, nullptr);
    // MLP up + GELU
    mlp_gemm_kernel<1><<<dim3(Fc / GBN, Mrows / GBM), NTHREADS, SMEM_MLP>>>(b1, nullptr);
    // MLP down + scalar residual
    mlp_gemm_kernel<2><<<dim3(Dc / GBN, Mrows / GBM), NTHREADS, SMEM_MLP>>>(b2, scalar);
    // LN2 -> output
    ln_kernel<2><<<Bc * Nt, 256>>>(ln2w, ln2b, out);
}

// round 4
// speedup vs baseline: 1.1074x; 1.1074x over previous
#include <cuda_runtime.h>
#include <cuda_bf16.h>
#include <cstdint>

using bf16 = __nv_bfloat16;

#define DEVI __device__ __forceinline__

constexpr int Bc = 4;      // batch
constexpr int Nt = 2048;   // tokens
constexpr int Dc = 1024;   // model dim
constexpr int Fc = 4096;   // ffn dim
constexpr int Mrows = Bc * Nt;   // 8192

constexpr int BM = 128, BN = 128, BK = 32;
constexpr int SA_ST   = BK + 8;    // 40
constexpr int SBKN_ST = BN + 8;    // 136
constexpr int NTHREADS = 256;

// ---------------- scratch ----------------------------------------------------
__device__ __align__(16) bf16  g_T[(size_t)Nt * Nt];
__device__ __align__(16) bf16  g_xb[(size_t)Bc * Nt * Dc];
__device__ __align__(16) float g_y1[(size_t)Bc * Nt * Dc];
__device__ __align__(16) float g_x1[(size_t)Bc * Nt * Dc];
__device__ __align__(16) bf16  g_x1b[(size_t)Bc * Nt * Dc];
__device__ __align__(16) bf16  g_W1b[(size_t)Fc * Dc];
__device__ __align__(16) bf16  g_W2b[(size_t)Dc * Fc];
__device__ __align__(16) bf16  g_H[(size_t)Bc * Nt * Fc];
__device__ __align__(16) float g_y2[(size_t)Bc * Nt * Dc];

// ---------------- PTX helpers -------------------------------------------------
DEVI uint32_t smem_u32(const void* p) {
    return static_cast<uint32_t>(__cvta_generic_to_shared(p));
}
DEVI void cp_async16(uint32_t sdst, const void* gsrc) {
    asm volatile("cp.async.cg.shared.global [%0], [%1], 16;\n" :: "r"(sdst), "l"(gsrc));
}
DEVI void cp_commit() { asm volatile("cp.async.commit_group;\n"); }
template <int N> DEVI void cp_wait() {
    asm volatile("cp.async.wait_group %0;\n" :: "n"(N));
}
DEVI void ldmx4(uint32_t& r0, uint32_t& r1, uint32_t& r2, uint32_t& r3, uint32_t a) {
    asm volatile("ldmatrix.sync.aligned.m8n8.x4.shared.b16 {%0,%1,%2,%3}, [%4];\n"
                 : "=r"(r0), "=r"(r1), "=r"(r2), "=r"(r3) : "r"(a));
}
DEVI void ldmx4t(uint32_t& r0, uint32_t& r1, uint32_t& r2, uint32_t& r3, uint32_t a) {
    asm volatile("ldmatrix.sync.aligned.m8n8.x4.trans.shared.b16 {%0,%1,%2,%3}, [%4];\n"
                 : "=r"(r0), "=r"(r1), "=r"(r2), "=r"(r3) : "r"(a));
}
DEVI void mma16816(float c[4], const uint32_t a[4], const uint32_t b[2]) {
    asm volatile(
        "mma.sync.aligned.m16n8k16.row.col.f32.bf16.bf16.f32 "
        "{%0,%1,%2,%3}, {%4,%5,%6,%7}, {%8,%9}, {%0,%1,%2,%3};\n"
        : "+f"(c[0]), "+f"(c[1]), "+f"(c[2]), "+f"(c[3])
        : "r"(a[0]), "r"(a[1]), "r"(a[2]), "r"(a[3]), "r"(b[0]), "r"(b[1]));
}
DEVI float gelu_exact(float v) {
    return 0.5f * v * (1.0f + erff(v * 0.70710678118654752f));
}

// ---------------- prep kernels ----------------------------------------------
template <int W>
__global__ void cvt_kernel(const float* __restrict__ src, int n4)
{
    bf16* dst = (W == 0) ? g_xb : (W == 1 ? g_W1b : g_W2b);
    int i = blockIdx.x * blockDim.x + threadIdx.x;
    if (i < n4) {
        float4 v = reinterpret_cast<const float4*>(src)[i];
        __nv_bfloat162* d2 = reinterpret_cast<__nv_bfloat162*>(dst) + 2 * (size_t)i;
        d2[0] = __floats2bfloat162_rn(v.x, v.y);
        d2[1] = __floats2bfloat162_rn(v.z, v.w);
    }
}

__global__ void buildT_kernel(const float* __restrict__ w)
{
    int i = blockIdx.x * blockDim.x + threadIdx.x;
    int n = i >> 11;
    int m = i & (Nt - 1);
    float v = (m <= n) ? w[n - m] : 0.0f;
    g_T[i] = __float2bfloat16(v);
}

// ---------------- conv GEMM (mma.sync, triangular K skip, 2 CTA/SM) -----------
__global__ void __launch_bounds__(NTHREADS, 2) conv_gemm_kernel(
    const float* __restrict__ x, const float* __restrict__ scale)
{
    constexpr int K = Nt;
    constexpr int Nc = Dc;

    const bf16* __restrict__ A  = g_T;
    const bf16* __restrict__ Bp = g_xb + (size_t)blockIdx.z * Nt * Dc;

    __shared__ __align__(16) bf16 sA[2][BM * SA_ST];     // 20 KB
    __shared__ __align__(16) bf16 sB[2][BK * SBKN_ST];   // 17 KB

    const int tid  = threadIdx.x;
    const int bm0  = blockIdx.y * BM;
    const int bn0  = blockIdx.x * BN;
    const int wid  = tid >> 5;
    const int lane = tid & 31;
    const int wm   = (wid & 3) * 32;
    const int wn   = (wid >> 2) * 64;
    const int kmax = (bm0 + BM) / BK;   // lower-triangular skip

    float acc[2][8][4];
#pragma unroll
    for (int i = 0; i < 2; i++)
#pragma unroll
        for (int j = 0; j < 8; j++)
#pragma unroll
            for (int q = 0; q < 4; q++) acc[i][j][q] = 0.0f;

    auto load_tiles = [&](int s, int kt) {
        const bf16* Ag = A + (size_t)bm0 * K + (size_t)kt * BK;
#pragma unroll
        for (int i = 0; i < 2; i++) {
            int ch  = tid + i * NTHREADS;
            int row = ch >> 2;
            int col = (ch & 3) * 8;
            cp_async16(smem_u32(&sA[s][row * SA_ST + col]), Ag + (size_t)row * K + col);
        }
        const bf16* Bg = Bp + (size_t)(kt * BK) * Nc + bn0;
#pragma unroll
        for (int i = 0; i < 2; i++) {
            int ch  = tid + i * NTHREADS;
            int row = ch >> 4;
            int col = (ch & 15) * 8;
            cp_async16(smem_u32(&sB[s][row * SBKN_ST + col]), Bg + (size_t)row * Nc + col);
        }
        cp_commit();
    };

    load_tiles(0, 0);

    for (int kt = 0; kt < kmax; kt++) {
        const int s = kt & 1;
        if (kt + 1 < kmax) { load_tiles(s ^ 1, kt + 1); cp_wait<1>(); }
        else               { cp_wait<0>(); }
        __syncthreads();

#pragma unroll
        for (int kk = 0; kk < BK; kk += 16) {
            uint32_t a[2][4];
#pragma unroll
            for (int i = 0; i < 2; i++) {
                const bf16* p = &sA[s][(wm + i * 16 + (lane & 15)) * SA_ST
                                       + kk + (lane >> 4) * 8];
                ldmx4(a[i][0], a[i][1], a[i][2], a[i][3], smem_u32(p));
            }
            uint32_t b[8][2];
#pragma unroll
            for (int j = 0; j < 8; j += 2) {
                uint32_t r0, r1, r2, r3;
                const bf16* p = &sB[s][(kk + (lane & 15)) * SBKN_ST
                                       + wn + j * 8 + (lane >> 4) * 8];
                ldmx4t(r0, r1, r2, r3, smem_u32(p));
                b[j][0] = r0; b[j][1] = r1; b[j + 1][0] = r2; b[j + 1][1] = r3;
            }
#pragma unroll
            for (int i = 0; i < 2; i++)
#pragma unroll
                for (int j = 0; j < 8; j++)
                    mma16816(acc[i][j], a[i], b[j]);
        }
        __syncthreads();
    }

    const int rbase = bm0 + wm + (lane >> 2);
    const int cbase = bn0 + wn + (lane & 3) * 2;
#pragma unroll
    for (int i = 0; i < 2; i++)
#pragma unroll
        for (int j = 0; j < 8; j++)
#pragma unroll
            for (int h = 0; h < 2; h++) {
                const int r = rbase + i * 16 + h * 8;
                const int c = cbase + j * 8;
                const size_t o = (size_t)blockIdx.z * (Nt * Dc) + (size_t)r * Dc + c;
                const float sc = scale[r];
                float2 ov = make_float2(x[o] + acc[i][j][h * 2] * sc,
                                        x[o + 1] + acc[i][j][h * 2 + 1] * sc);
                *reinterpret_cast<float2*>(g_y1 + o) = ov;
            }
}

// ---------------- MLP GEMM (mma.sync, 128x128 tile, 2 CTA/SM) ------------------
// EPI 1: A=g_x1b [8192,1024], B=g_W1b [4096,1024] K-major -> g_H = bf16(gelu(acc+b1))
// EPI 2: A=g_H   [8192,4096], B=g_W2b [1024,4096] K-major -> g_y2 = g_x1 + s*(acc+b2)
template <int EPI>
__global__ void __launch_bounds__(NTHREADS, 2) mlp_gemm_kernel(
    const float* __restrict__ bias, const float* __restrict__ scl)
{
    constexpr int K  = (EPI == 1) ? Dc : Fc;
    constexpr int KT = K / BK;

    const bf16* __restrict__ A = (EPI == 1) ? g_x1b : g_H;
    const bf16* __restrict__ B = (EPI == 1) ? g_W1b : g_W2b;

    __shared__ __align__(16) bf16 sA[2][BM * SA_ST];   // 20 KB
    __shared__ __align__(16) bf16 sB[2][BN * SA_ST];   // 20 KB

    const int tid  = threadIdx.x;
    const int wid  = tid >> 5;
    const int lane = tid & 31;
    const int bm0  = blockIdx.y * BM;
    const int bn0  = blockIdx.x * BN;
    const int wm   = (wid & 3) * 32;
    const int wn   = (wid >> 2) * 64;

    float acc[2][8][4];
#pragma unroll
    for (int i = 0; i < 2; i++)
#pragma unroll
        for (int j = 0; j < 8; j++)
#pragma unroll
            for (int q = 0; q < 4; q++) acc[i][j][q] = 0.0f;

    auto load_tiles = [&](int s, int kt) {
        const bf16* Ag = A + (size_t)bm0 * K + (size_t)kt * BK;
#pragma unroll
        for (int i = 0; i < 2; i++) {
            int ch  = tid + i * NTHREADS;
            int row = ch >> 2;
            int col = (ch & 3) * 8;
            cp_async16(smem_u32(&sA[s][row * SA_ST + col]), Ag + (size_t)row * K + col);
        }
        const bf16* Bg = B + (size_t)bn0 * K + (size_t)kt * BK;
#pragma unroll
        for (int i = 0; i < 2; i++) {
            int ch  = tid + i * NTHREADS;
            int row = ch >> 2;
            int col = (ch & 3) * 8;
            cp_async16(smem_u32(&sB[s][row * SA_ST + col]), Bg + (size_t)row * K + col);
        }
        cp_commit();
    };

    load_tiles(0, 0);

    for (int kt = 0; kt < KT; kt++) {
        const int s = kt & 1;
        if (kt + 1 < KT) { load_tiles(s ^ 1, kt + 1); cp_wait<1>(); }
        else             { cp_wait<0>(); }
        __syncthreads();

#pragma unroll
        for (int kk = 0; kk < BK; kk += 16) {
            uint32_t a[2][4];
#pragma unroll
            for (int i = 0; i < 2; i++) {
                const bf16* p = &sA[s][(wm + i * 16 + (lane & 15)) * SA_ST
                                       + kk + (lane >> 4) * 8];
                ldmx4(a[i][0], a[i][1], a[i][2], a[i][3], smem_u32(p));
            }
            uint32_t b[8][2];
#pragma unroll
            for (int j = 0; j < 8; j += 2) {
                uint32_t r0, r1, r2, r3;
                int rr = wn + j * 8 + ((lane >> 4) << 3) + (lane & 7);
                int cc = kk + ((lane >> 3) & 1) * 8;
                const bf16* p = &sB[s][rr * SA_ST + cc];
                ldmx4(r0, r1, r2, r3, smem_u32(p));
                b[j][0] = r0; b[j][1] = r1; b[j + 1][0] = r2; b[j + 1][1] = r3;
            }
#pragma unroll
            for (int i = 0; i < 2; i++)
#pragma unroll
                for (int j = 0; j < 8; j++)
                    mma16816(acc[i][j], a[i], b[j]);
        }
        __syncthreads();
    }

    // ---------------- epilogue ----------------
    float sscal = 0.0f;
    if constexpr (EPI == 2) sscal = scl[0];
    const int rbase = bm0 + wm + (lane >> 2);
    const int cbase = bn0 + wn + (lane & 3) * 2;

#pragma unroll
    for (int i = 0; i < 2; i++) {
#pragma unroll
        for (int j = 0; j < 8; j++) {
#pragma unroll
            for (int h = 0; h < 2; h++) {
                const int r = rbase + i * 16 + h * 8;
                const int c = cbase + j * 8;
                const float v0 = acc[i][j][h * 2 + 0];
                const float v1 = acc[i][j][h * 2 + 1];
                if constexpr (EPI == 1) {
                    const size_t o = (size_t)r * Fc + c;
                    __nv_bfloat162 hv = __floats2bfloat162_rn(
                        gelu_exact(v0 + bias[c]), gelu_exact(v1 + bias[c + 1]));
                    *reinterpret_cast<__nv_bfloat162*>(g_H + o) = hv;
                } else {
                    const size_t o = (size_t)r * Dc + c;
                    float2 xv = *reinterpret_cast<const float2*>(g_x1 + o);
                    float2 ov = make_float2(xv.x + sscal * (v0 + bias[c]),
                                            xv.y + sscal * (v1 + bias[c + 1]));
                    *reinterpret_cast<float2*>(g_y2 + o) = ov;
                }
            }
        }
    }
}

// ---------------- LayerNorm ---------------------------------------------------
template <int WHICH>
__global__ void __launch_bounds__(256) ln_kernel(
    const float* __restrict__ lw, const float* __restrict__ lb,
    float* __restrict__ outp)
{
    const float* __restrict__ in = (WHICH == 1) ? g_y1 : g_y2;
    const size_t row = blockIdx.x;
    const int t = threadIdx.x;

    float4 v = reinterpret_cast<const float4*>(in + row * Dc)[t];
    float s = v.x + v.y + v.z + v.w;
    float q = v.x * v.x + v.y * v.y + v.z * v.z + v.w * v.w;
#pragma unroll
    for (int o = 16; o > 0; o >>= 1) {
        s += __shfl_xor_sync(0xffffffffu, s, o);
        q += __shfl_xor_sync(0xffffffffu, q, o);
    }
    __shared__ float red[16];
    if ((t & 31) == 0) { red[t >> 5] = s; red[8 + (t >> 5)] = q; }
    __syncthreads();
    s = 0.0f; q = 0.0f;
#pragma unroll
    for (int i = 0; i < 8; i++) { s += red[i]; q += red[8 + i]; }

    const float mu  = s * (1.0f / Dc);
    const float inv = rsqrtf(q * (1.0f / Dc) - mu * mu + 1e-5f);
    const int c = t * 4;
    const float o0 = (v.x - mu) * inv * lw[c + 0] + lb[c + 0];
    const float o1 = (v.y - mu) * inv * lw[c + 1] + lb[c + 1];
    const float o2 = (v.z - mu) * inv * lw[c + 2] + lb[c + 2];
    const float o3 = (v.w - mu) * inv * lw[c + 3] + lb[c + 3];

    if constexpr (WHICH == 1) {
        reinterpret_cast<float4*>(g_x1 + row * Dc)[t] = make_float4(o0, o1, o2, o3);
        __nv_bfloat162* pb = reinterpret_cast<__nv_bfloat162*>(g_x1b + row * Dc) + t * 2;
        pb[0] = __floats2bfloat162_rn(o0, o1);
        pb[1] = __floats2bfloat162_rn(o2, o3);
    } else {
        reinterpret_cast<float4*>(outp + row * Dc)[t] = make_float4(o0, o1, o2, o3);
    }
}

// ---------------- launch --------------------------------------------------------
extern "C" void kernel_launch(void* const* d_in, const int* in_sizes, int n_in,
                              void* d_out, int out_size)
{
    const float* x       = (const float*)d_in[0];
    const float* weights = (const float*)d_in[1];
    const float* scale   = (const float*)d_in[2];
    const float* ln1w    = (const float*)d_in[3];
    const float* ln1b    = (const float*)d_in[4];
    const float* W1      = (const float*)d_in[5];
    const float* b1      = (const float*)d_in[6];
    const float* W2      = (const float*)d_in[7];
    const float* b2      = (const float*)d_in[8];
    const float* scalar  = (const float*)d_in[9];
    const float* ln2w    = (const float*)d_in[10];
    const float* ln2b    = (const float*)d_in[11];
    float* out = (float*)d_out;

    // prep
    {
        int n4x = Bc * Nt * Dc / 4;
        cvt_kernel<0><<<(n4x + 255) / 256, 256>>>(x, n4x);
        int n4w = Fc * Dc / 4;
        cvt_kernel<1><<<(n4w + 255) / 256, 256>>>(W1, n4w);
        cvt_kernel<2><<<(n4w + 255) / 256, 256>>>(W2, n4w);
        buildT_kernel<<<(Nt * Nt) / 256, 256>>>(weights);
    }

    // conv (triangular Toeplitz GEMM) + residual scale-add
    conv_gemm_kernel<<<dim3(Dc / BN, Nt / BM, Bc), NTHREADS>>>(x, scale);
    // LN1
    ln_kernel<1><<<Bc * Nt, 256>>>(ln1w, ln1b, nullptr);
    // MLP up + GELU
    mlp_gemm_kernel<1><<<dim3(Fc / BN, Mrows / BM), NTHREADS>>>(b1, nullptr);
    // MLP down + scalar residual
    mlp_gemm_kernel<2><<<dim3(Dc / BN, Mrows / BM), NTHREADS>>>(b2, scalar);
    // LN2 -> output
    ln_kernel<2><<<Bc * Nt, 256>>>(ln2w, ln2b, out);
}

// round 5
// speedup vs baseline: 1.1554x; 1.0434x over previous
#include <cuda_runtime.h>
#include <cuda_bf16.h>
#include <cuda_fp16.h>
#include <cstdint>

using bf16 = __nv_bfloat16;

#define DEVI __device__ __forceinline__

constexpr int Bc = 4;      // batch
constexpr int Nt = 2048;   // tokens
constexpr int Dc = 1024;   // model dim
constexpr int Fc = 4096;   // ffn dim
constexpr int Mrows = Bc * Nt;   // 8192

constexpr int BM = 128, BN = 128, BK = 32;
constexpr int SA_ST   = BK + 8;    // 40
constexpr int SBKN_ST = BN + 8;    // 136
constexpr int NTHREADS = 256;

// ---------------- scratch ----------------------------------------------------
__device__ __align__(16) bf16   g_T[(size_t)Nt * Nt];
__device__ __align__(16) bf16   g_xb[(size_t)Bc * Nt * Dc];
__device__ __align__(16) float  g_y1[(size_t)Bc * Nt * Dc];
__device__ __align__(16) float  g_x1[(size_t)Bc * Nt * Dc];
__device__ __align__(16) __half g_x1h[(size_t)Bc * Nt * Dc];
__device__ __align__(16) __half g_W1h[(size_t)Fc * Dc];
__device__ __align__(16) __half g_W2h[(size_t)Dc * Fc];
__device__ __align__(16) __half g_H[(size_t)Bc * Nt * Fc];
__device__ __align__(16) float  g_y2[(size_t)Bc * Nt * Dc];

// ---------------- PTX helpers -------------------------------------------------
DEVI uint32_t smem_u32(const void* p) {
    return static_cast<uint32_t>(__cvta_generic_to_shared(p));
}
DEVI void cp_async16(uint32_t sdst, const void* gsrc) {
    asm volatile("cp.async.cg.shared.global [%0], [%1], 16;\n" :: "r"(sdst), "l"(gsrc));
}
DEVI void cp_commit() { asm volatile("cp.async.commit_group;\n"); }
template <int N> DEVI void cp_wait() {
    asm volatile("cp.async.wait_group %0;\n" :: "n"(N));
}
DEVI void ldmx4(uint32_t& r0, uint32_t& r1, uint32_t& r2, uint32_t& r3, uint32_t a) {
    asm volatile("ldmatrix.sync.aligned.m8n8.x4.shared.b16 {%0,%1,%2,%3}, [%4];\n"
                 : "=r"(r0), "=r"(r1), "=r"(r2), "=r"(r3) : "r"(a));
}
DEVI void ldmx4t(uint32_t& r0, uint32_t& r1, uint32_t& r2, uint32_t& r3, uint32_t a) {
    asm volatile("ldmatrix.sync.aligned.m8n8.x4.trans.shared.b16 {%0,%1,%2,%3}, [%4];\n"
                 : "=r"(r0), "=r"(r1), "=r"(r2), "=r"(r3) : "r"(a));
}
// bf16 x bf16 -> f32
DEVI void mma16816_bf(float c[4], const uint32_t a[4], const uint32_t b[2]) {
    asm volatile(
        "mma.sync.aligned.m16n8k16.row.col.f32.bf16.bf16.f32 "
        "{%0,%1,%2,%3}, {%4,%5,%6,%7}, {%8,%9}, {%0,%1,%2,%3};\n"
        : "+f"(c[0]), "+f"(c[1]), "+f"(c[2]), "+f"(c[3])
        : "r"(a[0]), "r"(a[1]), "r"(a[2]), "r"(a[3]), "r"(b[0]), "r"(b[1]));
}
// f16 x f16 -> f32
DEVI void mma16816_hf32(float c[4], const uint32_t a[4], const uint32_t b[2]) {
    asm volatile(
        "mma.sync.aligned.m16n8k16.row.col.f32.f16.f16.f32 "
        "{%0,%1,%2,%3}, {%4,%5,%6,%7}, {%8,%9}, {%0,%1,%2,%3};\n"
        : "+f"(c[0]), "+f"(c[1]), "+f"(c[2]), "+f"(c[3])
        : "r"(a[0]), "r"(a[1]), "r"(a[2]), "r"(a[3]), "r"(b[0]), "r"(b[1]));
}
// f16 x f16 -> f16 (2-reg accumulator)
DEVI void mma16816_hf16(uint32_t c[2], const uint32_t a[4], const uint32_t b[2]) {
    asm volatile(
        "mma.sync.aligned.m16n8k16.row.col.f16.f16.f16.f16 "
        "{%0,%1}, {%2,%3,%4,%5}, {%6,%7}, {%0,%1};\n"
        : "+r"(c[0]), "+r"(c[1])
        : "r"(a[0]), "r"(a[1]), "r"(a[2]), "r"(a[3]), "r"(b[0]), "r"(b[1]));
}
DEVI float gelu_exact(float v) {
    return 0.5f * v * (1.0f + erff(v * 0.70710678118654752f));
}

// ---------------- prep kernels ----------------------------------------------
__global__ void cvt_x_kernel(const float* __restrict__ src, int n4)
{
    int i = blockIdx.x * blockDim.x + threadIdx.x;
    if (i < n4) {
        float4 v = reinterpret_cast<const float4*>(src)[i];
        __nv_bfloat162* d2 = reinterpret_cast<__nv_bfloat162*>(g_xb) + 2 * (size_t)i;
        d2[0] = __floats2bfloat162_rn(v.x, v.y);
        d2[1] = __floats2bfloat162_rn(v.z, v.w);
    }
}

template <int W>
__global__ void cvt_w_kernel(const float* __restrict__ src, int n4)
{
    __half* dst = (W == 1) ? g_W1h : g_W2h;
    int i = blockIdx.x * blockDim.x + threadIdx.x;
    if (i < n4) {
        float4 v = reinterpret_cast<const float4*>(src)[i];
        __half2* d2 = reinterpret_cast<__half2*>(dst) + 2 * (size_t)i;
        d2[0] = __floats2half2_rn(v.x, v.y);
        d2[1] = __floats2half2_rn(v.z, v.w);
    }
}

__global__ void buildT_kernel(const float* __restrict__ w)
{
    int i = blockIdx.x * blockDim.x + threadIdx.x;
    int n = i >> 11;
    int m = i & (Nt - 1);
    float v = (m <= n) ? w[n - m] : 0.0f;
    g_T[i] = __float2bfloat16(v);
}

// ---------------- conv GEMM (bf16, f32 acc, triangular K skip) ----------------
__global__ void __launch_bounds__(NTHREADS, 2) conv_gemm_kernel(
    const float* __restrict__ x, const float* __restrict__ scale)
{
    constexpr int K = Nt;
    constexpr int Nc = Dc;

    const bf16* __restrict__ A  = g_T;
    const bf16* __restrict__ Bp = g_xb + (size_t)blockIdx.z * Nt * Dc;

    __shared__ __align__(16) bf16 sA[2][BM * SA_ST];
    __shared__ __align__(16) bf16 sB[2][BK * SBKN_ST];

    const int tid  = threadIdx.x;
    const int bm0  = blockIdx.y * BM;
    const int bn0  = blockIdx.x * BN;
    const int wid  = tid >> 5;
    const int lane = tid & 31;
    const int wm   = (wid & 3) * 32;
    const int wn   = (wid >> 2) * 64;
    const int kmax = (bm0 + BM) / BK;

    float acc[2][8][4];
#pragma unroll
    for (int i = 0; i < 2; i++)
#pragma unroll
        for (int j = 0; j < 8; j++)
#pragma unroll
            for (int q = 0; q < 4; q++) acc[i][j][q] = 0.0f;

    auto load_tiles = [&](int s, int kt) {
        const bf16* Ag = A + (size_t)bm0 * K + (size_t)kt * BK;
#pragma unroll
        for (int i = 0; i < 2; i++) {
            int ch  = tid + i * NTHREADS;
            int row = ch >> 2;
            int col = (ch & 3) * 8;
            cp_async16(smem_u32(&sA[s][row * SA_ST + col]), Ag + (size_t)row * K + col);
        }
        const bf16* Bg = Bp + (size_t)(kt * BK) * Nc + bn0;
#pragma unroll
        for (int i = 0; i < 2; i++) {
            int ch  = tid + i * NTHREADS;
            int row = ch >> 4;
            int col = (ch & 15) * 8;
            cp_async16(smem_u32(&sB[s][row * SBKN_ST + col]), Bg + (size_t)row * Nc + col);
        }
        cp_commit();
    };

    load_tiles(0, 0);

    for (int kt = 0; kt < kmax; kt++) {
        const int s = kt & 1;
        if (kt + 1 < kmax) { load_tiles(s ^ 1, kt + 1); cp_wait<1>(); }
        else               { cp_wait<0>(); }
        __syncthreads();

#pragma unroll
        for (int kk = 0; kk < BK; kk += 16) {
            uint32_t a[2][4];
#pragma unroll
            for (int i = 0; i < 2; i++) {
                const bf16* p = &sA[s][(wm + i * 16 + (lane & 15)) * SA_ST
                                       + kk + (lane >> 4) * 8];
                ldmx4(a[i][0], a[i][1], a[i][2], a[i][3], smem_u32(p));
            }
            uint32_t b[8][2];
#pragma unroll
            for (int j = 0; j < 8; j += 2) {
                uint32_t r0, r1, r2, r3;
                const bf16* p = &sB[s][(kk + (lane & 15)) * SBKN_ST
                                       + wn + j * 8 + (lane >> 4) * 8];
                ldmx4t(r0, r1, r2, r3, smem_u32(p));
                b[j][0] = r0; b[j][1] = r1; b[j + 1][0] = r2; b[j + 1][1] = r3;
            }
#pragma unroll
            for (int i = 0; i < 2; i++)
#pragma unroll
                for (int j = 0; j < 8; j++)
                    mma16816_bf(acc[i][j], a[i], b[j]);
        }
        __syncthreads();
    }

    const int rbase = bm0 + wm + (lane >> 2);
    const int cbase = bn0 + wn + (lane & 3) * 2;
#pragma unroll
    for (int i = 0; i < 2; i++)
#pragma unroll
        for (int j = 0; j < 8; j++)
#pragma unroll
            for (int h = 0; h < 2; h++) {
                const int r = rbase + i * 16 + h * 8;
                const int c = cbase + j * 8;
                const size_t o = (size_t)blockIdx.z * (Nt * Dc) + (size_t)r * Dc + c;
                const float sc = scale[r];
                float2 ov = make_float2(x[o] + acc[i][j][h * 2] * sc,
                                        x[o + 1] + acc[i][j][h * 2 + 1] * sc);
                *reinterpret_cast<float2*>(g_y1 + o) = ov;
            }
}

// ---------------- MLP GEMM 1 (f16 inputs, f16 accumulation) --------------------
// A=g_x1h [8192,1024], B=g_W1h [4096,1024] -> g_H = half(gelu(acc+b1))
__global__ void __launch_bounds__(NTHREADS, 2) mlp1_gemm_kernel(
    const float* __restrict__ bias)
{
    constexpr int K  = Dc;
    constexpr int KT = K / BK;

    const __half* __restrict__ A = g_x1h;
    const __half* __restrict__ B = g_W1h;

    __shared__ __align__(16) __half sA[2][BM * SA_ST];
    __shared__ __align__(16) __half sB[2][BN * SA_ST];

    const int tid  = threadIdx.x;
    const int wid  = tid >> 5;
    const int lane = tid & 31;
    const int bm0  = blockIdx.y * BM;
    const int bn0  = blockIdx.x * BN;
    const int wm   = (wid & 3) * 32;
    const int wn   = (wid >> 2) * 64;

    uint32_t acc[2][8][2];
#pragma unroll
    for (int i = 0; i < 2; i++)
#pragma unroll
        for (int j = 0; j < 8; j++) { acc[i][j][0] = 0u; acc[i][j][1] = 0u; }

    auto load_tiles = [&](int s, int kt) {
        const __half* Ag = A + (size_t)bm0 * K + (size_t)kt * BK;
#pragma unroll
        for (int i = 0; i < 2; i++) {
            int ch  = tid + i * NTHREADS;
            int row = ch >> 2;
            int col = (ch & 3) * 8;
            cp_async16(smem_u32(&sA[s][row * SA_ST + col]), Ag + (size_t)row * K + col);
        }
        const __half* Bg = B + (size_t)bn0 * K + (size_t)kt * BK;
#pragma unroll
        for (int i = 0; i < 2; i++) {
            int ch  = tid + i * NTHREADS;
            int row = ch >> 2;
            int col = (ch & 3) * 8;
            cp_async16(smem_u32(&sB[s][row * SA_ST + col]), Bg + (size_t)row * K + col);
        }
        cp_commit();
    };

    load_tiles(0, 0);

    for (int kt = 0; kt < KT; kt++) {
        const int s = kt & 1;
        if (kt + 1 < KT) { load_tiles(s ^ 1, kt + 1); cp_wait<1>(); }
        else             { cp_wait<0>(); }
        __syncthreads();

#pragma unroll
        for (int kk = 0; kk < BK; kk += 16) {
            uint32_t a[2][4];
#pragma unroll
            for (int i = 0; i < 2; i++) {
                const __half* p = &sA[s][(wm + i * 16 + (lane & 15)) * SA_ST
                                         + kk + (lane >> 4) * 8];
                ldmx4(a[i][0], a[i][1], a[i][2], a[i][3], smem_u32(p));
            }
            uint32_t b[8][2];
#pragma unroll
            for (int j = 0; j < 8; j += 2) {
                uint32_t r0, r1, r2, r3;
                int rr = wn + j * 8 + ((lane >> 4) << 3) + (lane & 7);
                int cc = kk + ((lane >> 3) & 1) * 8;
                const __half* p = &sB[s][rr * SA_ST + cc];
                ldmx4(r0, r1, r2, r3, smem_u32(p));
                b[j][0] = r0; b[j][1] = r1; b[j + 1][0] = r2; b[j + 1][1] = r3;
            }
#pragma unroll
            for (int i = 0; i < 2; i++)
#pragma unroll
                for (int j = 0; j < 8; j++)
                    mma16816_hf16(acc[i][j], a[i], b[j]);
        }
        __syncthreads();
    }

    // epilogue: unpack f16 acc, add bias, exact gelu, store half
    const int rbase = bm0 + wm + (lane >> 2);
    const int cbase = bn0 + wn + (lane & 3) * 2;
#pragma unroll
    for (int i = 0; i < 2; i++) {
#pragma unroll
        for (int j = 0; j < 8; j++) {
#pragma unroll
            for (int h = 0; h < 2; h++) {
                const int r = rbase + i * 16 + h * 8;
                const int c = cbase + j * 8;
                __half2 hv = *reinterpret_cast<const __half2*>(&acc[i][j][h]);
                float v0 = __half2float(__low2half(hv))  + bias[c];
                float v1 = __half2float(__high2half(hv)) + bias[c + 1];
                __half2 ov = __floats2half2_rn(gelu_exact(v0), gelu_exact(v1));
                *reinterpret_cast<__half2*>(g_H + (size_t)r * Fc + c) = ov;
            }
        }
    }
}

// ---------------- MLP GEMM 2 (f16 inputs, f32 accumulation) --------------------
// A=g_H [8192,4096], B=g_W2h [1024,4096] -> g_y2 = g_x1 + s*(acc+b2)
__global__ void __launch_bounds__(NTHREADS, 2) mlp2_gemm_kernel(
    const float* __restrict__ bias, const float* __restrict__ scl)
{
    constexpr int K  = Fc;
    constexpr int KT = K / BK;

    const __half* __restrict__ A = g_H;
    const __half* __restrict__ B = g_W2h;

    __shared__ __align__(16) __half sA[2][BM * SA_ST];
    __shared__ __align__(16) __half sB[2][BN * SA_ST];

    const int tid  = threadIdx.x;
    const int wid  = tid >> 5;
    const int lane = tid & 31;
    const int bm0  = blockIdx.y * BM;
    const int bn0  = blockIdx.x * BN;
    const int wm   = (wid & 3) * 32;
    const int wn   = (wid >> 2) * 64;

    float acc[2][8][4];
#pragma unroll
    for (int i = 0; i < 2; i++)
#pragma unroll
        for (int j = 0; j < 8; j++)
#pragma unroll
            for (int q = 0; q < 4; q++) acc[i][j][q] = 0.0f;

    auto load_tiles = [&](int s, int kt) {
        const __half* Ag = A + (size_t)bm0 * K + (size_t)kt * BK;
#pragma unroll
        for (int i = 0; i < 2; i++) {
            int ch  = tid + i * NTHREADS;
            int row = ch >> 2;
            int col = (ch & 3) * 8;
            cp_async16(smem_u32(&sA[s][row * SA_ST + col]), Ag + (size_t)row * K + col);
        }
        const __half* Bg = B + (size_t)bn0 * K + (size_t)kt * BK;
#pragma unroll
        for (int i = 0; i < 2; i++) {
            int ch  = tid + i * NTHREADS;
            int row = ch >> 2;
            int col = (ch & 3) * 8;
            cp_async16(smem_u32(&sB[s][row * SA_ST + col]), Bg + (size_t)row * K + col);
        }
        cp_commit();
    };

    load_tiles(0, 0);

    for (int kt = 0; kt < KT; kt++) {
        const int s = kt & 1;
        if (kt + 1 < KT) { load_tiles(s ^ 1, kt + 1); cp_wait<1>(); }
        else             { cp_wait<0>(); }
        __syncthreads();

#pragma unroll
        for (int kk = 0; kk < BK; kk += 16) {
            uint32_t a[2][4];
#pragma unroll
            for (int i = 0; i < 2; i++) {
                const __half* p = &sA[s][(wm + i * 16 + (lane & 15)) * SA_ST
                                         + kk + (lane >> 4) * 8];
                ldmx4(a[i][0], a[i][1], a[i][2], a[i][3], smem_u32(p));
            }
            uint32_t b[8][2];
#pragma unroll
            for (int j = 0; j < 8; j += 2) {
                uint32_t r0, r1, r2, r3;
                int rr = wn + j * 8 + ((lane >> 4) << 3) + (lane & 7);
                int cc = kk + ((lane >> 3) & 1) * 8;
                const __half* p = &sB[s][rr * SA_ST + cc];
                ldmx4(r0, r1, r2, r3, smem_u32(p));
                b[j][0] = r0; b[j][1] = r1; b[j + 1][0] = r2; b[j + 1][1] = r3;
            }
#pragma unroll
            for (int i = 0; i < 2; i++)
#pragma unroll
                for (int j = 0; j < 8; j++)
                    mma16816_hf32(acc[i][j], a[i], b[j]);
        }
        __syncthreads();
    }

    float sscal = scl[0];
    const int rbase = bm0 + wm + (lane >> 2);
    const int cbase = bn0 + wn + (lane & 3) * 2;
#pragma unroll
    for (int i = 0; i < 2; i++)
#pragma unroll
        for (int j = 0; j < 8; j++)
#pragma unroll
            for (int h = 0; h < 2; h++) {
                const int r = rbase + i * 16 + h * 8;
                const int c = cbase + j * 8;
                const size_t o = (size_t)r * Dc + c;
                float2 xv = *reinterpret_cast<const float2*>(g_x1 + o);
                float2 ov = make_float2(
                    xv.x + sscal * (acc[i][j][h * 2]     + bias[c]),
                    xv.y + sscal * (acc[i][j][h * 2 + 1] + bias[c + 1]));
                *reinterpret_cast<float2*>(g_y2 + o) = ov;
            }
}

// ---------------- LayerNorm ---------------------------------------------------
template <int WHICH>
__global__ void __launch_bounds__(256) ln_kernel(
    const float* __restrict__ lw, const float* __restrict__ lb,
    float* __restrict__ outp)
{
    const float* __restrict__ in = (WHICH == 1) ? g_y1 : g_y2;
    const size_t row = blockIdx.x;
    const int t = threadIdx.x;

    float4 v = reinterpret_cast<const float4*>(in + row * Dc)[t];
    float s = v.x + v.y + v.z + v.w;
    float q = v.x * v.x + v.y * v.y + v.z * v.z + v.w * v.w;
#pragma unroll
    for (int o = 16; o > 0; o >>= 1) {
        s += __shfl_xor_sync(0xffffffffu, s, o);
        q += __shfl_xor_sync(0xffffffffu, q, o);
    }
    __shared__ float red[16];
    if ((t & 31) == 0) { red[t >> 5] = s; red[8 + (t >> 5)] = q; }
    __syncthreads();
    s = 0.0f; q = 0.0f;
#pragma unroll
    for (int i = 0; i < 8; i++) { s += red[i]; q += red[8 + i]; }

    const float mu  = s * (1.0f / Dc);
    const float inv = rsqrtf(q * (1.0f / Dc) - mu * mu + 1e-5f);
    const int c = t * 4;
    const float o0 = (v.x - mu) * inv * lw[c + 0] + lb[c + 0];
    const float o1 = (v.y - mu) * inv * lw[c + 1] + lb[c + 1];
    const float o2 = (v.z - mu) * inv * lw[c + 2] + lb[c + 2];
    const float o3 = (v.w - mu) * inv * lw[c + 3] + lb[c + 3];

    if constexpr (WHICH == 1) {
        reinterpret_cast<float4*>(g_x1 + row * Dc)[t] = make_float4(o0, o1, o2, o3);
        __half2* ph = reinterpret_cast<__half2*>(g_x1h + row * Dc) + t * 2;
        ph[0] = __floats2half2_rn(o0, o1);
        ph[1] = __floats2half2_rn(o2, o3);
    } else {
        reinterpret_cast<float4*>(outp + row * Dc)[t] = make_float4(o0, o1, o2, o3);
    }
}

// ---------------- launch --------------------------------------------------------
extern "C" void kernel_launch(void* const* d_in, const int* in_sizes, int n_in,
                              void* d_out, int out_size)
{
    const float* x       = (const float*)d_in[0];
    const float* weights = (const float*)d_in[1];
    const float* scale   = (const float*)d_in[2];
    const float* ln1w    = (const float*)d_in[3];
    const float* ln1b    = (const float*)d_in[4];
    const float* W1      = (const float*)d_in[5];
    const float* b1      = (const float*)d_in[6];
    const float* W2      = (const float*)d_in[7];
    const float* b2      = (const float*)d_in[8];
    const float* scalar  = (const float*)d_in[9];
    const float* ln2w    = (const float*)d_in[10];
    const float* ln2b    = (const float*)d_in[11];
    float* out = (float*)d_out;

    // prep
    {
        int n4x = Bc * Nt * Dc / 4;
        cvt_x_kernel<<<(n4x + 255) / 256, 256>>>(x, n4x);
        int n4w = Fc * Dc / 4;
        cvt_w_kernel<1><<<(n4w + 255) / 256, 256>>>(W1, n4w);
        cvt_w_kernel<2><<<(n4w + 255) / 256, 256>>>(W2, n4w);
        buildT_kernel<<<(Nt * Nt) / 256, 256>>>(weights);
    }

    // conv (triangular Toeplitz GEMM) + residual scale-add
    conv_gemm_kernel<<<dim3(Dc / BN, Nt / BM, Bc), NTHREADS>>>(x, scale);
    // LN1
    ln_kernel<1><<<Bc * Nt, 256>>>(ln1w, ln1b, nullptr);
    // MLP up + GELU (f16 accumulate)
    mlp1_gemm_kernel<<<dim3(Fc / BN, Mrows / BM), NTHREADS>>>(b1);
    // MLP down + scalar residual (f32 accumulate)
    mlp2_gemm_kernel<<<dim3(Dc / BN, Mrows / BM), NTHREADS>>>(b2, scalar);
    // LN2 -> output
    ln_kernel<2><<<Bc * Nt, 256>>>(ln2w, ln2b, out);
}